// round 13
// baseline (speedup 1.0000x reference)
#include <cuda_runtime.h>
#include <cuda_fp16.h>
#include <cstdint>

#define BN    16384
#define HIDD  256
#define NHEAD 4
#define DHEAD 64
#define BATCH 8
#define SEQ   2048
#define CATD  288   // HID + POS

// ---------------- scratch (device globals; no allocation allowed) -------------
__device__ __half g_ip[BN * CATD];
__device__ __half g_qp[BN * CATD];
__device__ __half g_Wc[3 * HIDD * CATD];
__device__ __half g_wo[HIDD * HIDD];
__device__ __half g_q[BN * HIDD];
__device__ __half g_k[BN * HIDD];
__device__ __half g_v[BN * HIDD];
__device__ __half g_o[BN * HIDD];
__device__ float  g_o2[BN * HIDD];

// ---------------- helpers -----------------------------------------------------
__device__ __forceinline__ void mma_f16(float c[4], uint32_t a0, uint32_t a1,
                                        uint32_t a2, uint32_t a3,
                                        uint32_t b0, uint32_t b1) {
    asm volatile(
        "mma.sync.aligned.m16n8k16.row.col.f32.f16.f16.f32 "
        "{%0,%1,%2,%3}, {%4,%5,%6,%7}, {%8,%9}, {%0,%1,%2,%3};\n"
        : "+f"(c[0]), "+f"(c[1]), "+f"(c[2]), "+f"(c[3])
        : "r"(a0), "r"(a1), "r"(a2), "r"(a3), "r"(b0), "r"(b1));
}
__device__ __forceinline__ void ldsm_x4(uint32_t& r0, uint32_t& r1,
                                        uint32_t& r2, uint32_t& r3, uint32_t addr) {
    asm volatile("ldmatrix.sync.aligned.m8n8.x4.shared.b16 {%0,%1,%2,%3}, [%4];"
                 : "=r"(r0), "=r"(r1), "=r"(r2), "=r"(r3) : "r"(addr));
}
__device__ __forceinline__ void ldsm_x4_trans(uint32_t& r0, uint32_t& r1,
                                              uint32_t& r2, uint32_t& r3, uint32_t addr) {
    asm volatile("ldmatrix.sync.aligned.m8n8.x4.trans.shared.b16 {%0,%1,%2,%3}, [%4];"
                 : "=r"(r0), "=r"(r1), "=r"(r2), "=r"(r3) : "r"(addr));
}
__device__ __forceinline__ uint32_t ex2h2(float a, float b) {
    __half2 h = __floats2half2_rn(a, b);
    uint32_t in = *(uint32_t*)&h, out;
    asm("ex2.approx.f16x2 %0, %1;" : "=r"(out) : "r"(in));
    return out;
}
__device__ __forceinline__ uint32_t packh2(float a, float b) {
    __half2 h = __floats2half2_rn(a, b);
    return *(uint32_t*)&h;
}
__device__ __forceinline__ void cpasync16(uint32_t saddr, const void* g) {
    asm volatile("cp.async.cg.shared.global [%0], [%1], 16;" :: "r"(saddr), "l"(g));
}

// ---------------- pos2embed + 2-layer MLP (both coord sets in one launch) ----
__global__ void pos_mlp_kernel(const float* __restrict__ coordsA,
                               const float* __restrict__ coordsB,
                               const float* __restrict__ w1, const float* __restrict__ b1,
                               const float* __restrict__ w2, const float* __restrict__ b2,
                               __half* __restrict__ outA, __half* __restrict__ outB) {
    __shared__ float e_sh[4][96];
    __shared__ float h_sh[4][32];
    const int warp = threadIdx.x >> 5;
    const int lane = threadIdx.x & 31;
    const int n = blockIdx.x * 4 + warp;
    const float* coords = blockIdx.y ? coordsB : coordsA;
    __half* out = blockIdx.y ? outB : outA;

    const float TWO_PI = 6.283185307179586f;
    const float* c = coords + (size_t)n * 4;
    const float px = c[1] * TWO_PI;
    const float py = c[2] * TWO_PI;
    const float pz = c[3] * TWO_PI;

    const float dimt = 1.0f + (float)(lane >> 1) * (1.0f / 16.0f);
    const bool even = (lane & 1) == 0;
    // order (ey, ex, ez); NOTE reference bug: ez odd entries use cos(px)
    e_sh[warp][lane]      = even ? sinf(py / dimt) : cosf(py / dimt);
    e_sh[warp][32 + lane] = even ? sinf(px / dimt) : cosf(px / dimt);
    e_sh[warp][64 + lane] = even ? sinf(pz / dimt) : cosf(px / dimt);
    __syncwarp();

    float h = b1[lane];
    #pragma unroll 8
    for (int j = 0; j < 96; j++) h = fmaf(e_sh[warp][j], w1[lane * 96 + j], h);
    h_sh[warp][lane] = fmaxf(h, 0.0f);
    __syncwarp();

    float o = b2[lane];
    #pragma unroll
    for (int j = 0; j < 32; j++) o = fmaf(h_sh[warp][j], w2[lane * 32 + j], o);
    out[(size_t)n * CATD + HIDD + lane] = __float2half_rn(o);
}

// ---------------- fp32 rows -> fp16 rows inside 288-stride concat buffer -----
__global__ void concat_copy_kernel(const float* __restrict__ srcA, __half* __restrict__ dstA,
                                   const float* __restrict__ srcB, __half* __restrict__ dstB) {
    const float* src = blockIdx.y ? srcB : srcA;
    __half* dst = blockIdx.y ? dstB : dstA;
    int idx = blockIdx.x * blockDim.x + threadIdx.x;
    int n = idx >> 6, c4 = idx & 63;
    float4 v = ((const float4*)src)[(size_t)n * 64 + c4];
    uint2 u;
    u.x = packh2(v.x, v.y);
    u.y = packh2(v.z, v.w);
    *(uint2*)&dst[(size_t)n * CATD + c4 * 4] = u;
}

// ---------------- fp32 -> fp16 plain convert ---------------------------------
__global__ void f2h_kernel(const float* __restrict__ s, __half* __restrict__ d) {
    int i = blockIdx.x * blockDim.x + threadIdx.x;
    float4 v = ((const float4*)s)[i];
    uint2 u;
    u.x = packh2(v.x, v.y);
    u.y = packh2(v.z, v.w);
    *(uint2*)&d[(size_t)i * 4] = u;
}

// ---------------- Wc[m] = in_proj_w[m] @ W_m   (256x288), half out -----------
__global__ void wcombine_kernel(const float* __restrict__ in_proj_w,
                                const float* __restrict__ Wq,
                                const float* __restrict__ Wk,
                                const float* __restrict__ Wv,
                                __half* __restrict__ Wc) {
    const int m = blockIdx.z;
    const float* W = (m == 0) ? Wq : ((m == 1) ? Wk : Wv);
    const float* A = in_proj_w + (size_t)m * HIDD * HIDD;
    __shared__ float As[16][17];
    __shared__ float Bs[16][17];
    const int tx = threadIdx.x, ty = threadIdx.y;
    const int row = blockIdx.y * 16 + ty;
    const int col = blockIdx.x * 16 + tx;
    float acc = 0.0f;
    for (int kt = 0; kt < HIDD; kt += 16) {
        As[ty][tx] = A[row * HIDD + kt + tx];
        Bs[ty][tx] = W[(kt + ty) * CATD + col];
        __syncthreads();
        #pragma unroll
        for (int kk = 0; kk < 16; kk++) acc = fmaf(As[ty][kk], Bs[kk][tx], acc);
        __syncthreads();
    }
    Wc[(size_t)m * HIDD * CATD + row * CATD + col] = __float2half_rn(acc);
}

// ---------------- fp16 GEMM body: C[M,256] = (A@W^T + bias)*scale ------------
#define GST 40
template<int HOUT>
__device__ __forceinline__ void gemm_body(
        const __half* __restrict__ A, int K,
        const __half* __restrict__ W, const float* __restrict__ bias,
        float scale, void* __restrict__ Cv,
        __half* As, __half* Ws) {
    const int tid = threadIdx.x;
    const int w = tid >> 5, lane = tid & 31;
    const int gid = lane >> 2, tig = lane & 3;
    const int wr = w >> 1, wc = w & 1;
    const int m0 = blockIdx.y * 64, n0 = blockIdx.x * 64;
    float acc[4][4] = {};
    const int lr = tid >> 2, le8 = (tid & 3) * 8;
    for (int kt = 0; kt < K; kt += 32) {
        *(uint4*)&As[lr * GST + le8] = *(const uint4*)&A[(size_t)(m0 + lr) * K + kt + le8];
        *(uint4*)&Ws[lr * GST + le8] = *(const uint4*)&W[(size_t)(n0 + lr) * K + kt + le8];
        __syncthreads();
        #pragma unroll
        for (int kk = 0; kk < 2; kk++) {
            uint32_t a0 = *(uint32_t*)&As[(wr * 16 + gid) * GST + kk * 16 + 2 * tig];
            uint32_t a1 = *(uint32_t*)&As[(wr * 16 + gid + 8) * GST + kk * 16 + 2 * tig];
            uint32_t a2 = *(uint32_t*)&As[(wr * 16 + gid) * GST + kk * 16 + 2 * tig + 8];
            uint32_t a3 = *(uint32_t*)&As[(wr * 16 + gid + 8) * GST + kk * 16 + 2 * tig + 8];
            #pragma unroll
            for (int nb = 0; nb < 4; nb++) {
                uint32_t b0 = *(uint32_t*)&Ws[(wc * 32 + nb * 8 + gid) * GST + kk * 16 + 2 * tig];
                uint32_t b1 = *(uint32_t*)&Ws[(wc * 32 + nb * 8 + gid) * GST + kk * 16 + 2 * tig + 8];
                mma_f16(acc[nb], a0, a1, a2, a3, b0, b1);
            }
        }
        __syncthreads();
    }
    #pragma unroll
    for (int nb = 0; nb < 4; nb++) {
        int col = n0 + wc * 32 + nb * 8 + 2 * tig;
        float b0 = bias[col], b1 = bias[col + 1];
        float v00 = (acc[nb][0] + b0) * scale, v01 = (acc[nb][1] + b1) * scale;
        float v10 = (acc[nb][2] + b0) * scale, v11 = (acc[nb][3] + b1) * scale;
        int row0 = m0 + wr * 16 + gid;
        if (HOUT) {
            __half* C = (__half*)Cv;
            *(uint32_t*)&C[(size_t)row0 * HIDD + col] = packh2(v00, v01);
            *(uint32_t*)&C[(size_t)(row0 + 8) * HIDD + col] = packh2(v10, v11);
        } else {
            float* C = (float*)Cv;
            *(float2*)&C[(size_t)row0 * HIDD + col] = make_float2(v00, v01);
            *(float2*)&C[(size_t)(row0 + 8) * HIDD + col] = make_float2(v10, v11);
        }
    }
}

// merged q/k/v projection: blockIdx.z selects target
__global__ __launch_bounds__(256) void gemm_qkv_kernel(
        const __half* __restrict__ qp, const __half* __restrict__ ip,
        const __half* __restrict__ Wc, const float* __restrict__ in_proj_b,
        float qscale,
        __half* __restrict__ qd, __half* __restrict__ kd, __half* __restrict__ vd) {
    __shared__ __half As[64 * GST];
    __shared__ __half Ws[64 * GST];
    const int z = blockIdx.z;
    const __half* A = (z == 0) ? qp : ip;
    __half* C = (z == 0) ? qd : ((z == 1) ? kd : vd);
    gemm_body<1>(A, CATD, Wc + (size_t)z * HIDD * CATD, in_proj_b + z * HIDD,
                 (z == 0) ? qscale : 1.0f, C, As, Ws);
}

__global__ __launch_bounds__(256) void gemm_out_kernel(
        const __half* __restrict__ A, const __half* __restrict__ W,
        const float* __restrict__ bias, float* __restrict__ C) {
    __shared__ __half As[64 * GST];
    __shared__ __half Ws[64 * GST];
    gemm_body<0>(A, HIDD, W, bias, 1.0f, C, As, Ws);
}

// ---------------- flash attention, fp16 mma, register-resident P -------------
// grid (SEQ/128, B*H), block 256 (8 warps x 16 q rows). Q pre-scaled log2e/8.
// smem: Q[128xAST] + double-buffered K,V[64xAST each]
#define AST 88
#define NT  (SEQ / 64)
__global__ __launch_bounds__(256, 2) void attn_h_kernel(
        const __half* __restrict__ q, const __half* __restrict__ k,
        const __half* __restrict__ v, __half* __restrict__ o) {
    extern __shared__ __half sm[];
    __half* Qs = sm;                                  // 128 x AST
    // K/V stage c: sm + (128 + 128*c)*AST , V offset +64*AST
    const int tid = threadIdx.x;
    const int w = tid >> 5, lane = tid & 31;
    const int gid = lane >> 2, tig = lane & 3;
    const int bh = blockIdx.y;
    const int b = bh >> 2, h = bh & 3;
    const int q0 = blockIdx.x * 128;
    const size_t base = (size_t)b * SEQ * HIDD + h * DHEAD;
    const __half* qb = q + base;
    const __half* kb = k + base;
    const __half* vb = v + base;

    const uint32_t smbase = (uint32_t)__cvta_generic_to_shared(sm);
    const int ldr = tid >> 3, lde8 = (tid & 7) * 8;   // 256 thr -> 32 rows x 8 chunks? (64 rows: 2 iters)

    // load Q tile to smem
    #pragma unroll
    for (int u = 0; u < 4; u++) {
        int f = tid + u * 256;
        int r = f >> 3, e8 = (f & 7) * 8;
        *(uint4*)&Qs[r * AST + e8] = *(const uint4*)&qb[(size_t)(q0 + r) * HIDD + e8];
    }

    // prologue: async-load K/V tile 0 into stage 0
    {
        const uint32_t kst = smbase + 2u * (128u * AST);
        const uint32_t vst = kst + 2u * (64u * AST);
        #pragma unroll
        for (int u = 0; u < 2; u++) {
            int f = tid + u * 256;
            int r = f >> 3, e8 = (f & 7) * 8;
            cpasync16(kst + 2u * (r * AST + e8), &kb[(size_t)r * HIDD + e8]);
            cpasync16(vst + 2u * (r * AST + e8), &vb[(size_t)r * HIDD + e8]);
        }
        asm volatile("cp.async.commit_group;");
    }
    __syncthreads();   // Qs visible

    // preload Q A-fragments (4 k-blocks of 16)
    uint32_t qa[4][4];
    {
        const uint32_t qsb = smbase;
        const int row = w * 16 + (lane & 15);
        const int ko = (lane >> 4) * 8;
        #pragma unroll
        for (int kk = 0; kk < 4; kk++) {
            uint32_t addr = qsb + 2u * (uint32_t)(row * AST + kk * 16 + ko);
            ldsm_x4(qa[kk][0], qa[kk][1], qa[kk][2], qa[kk][3], addr);
        }
    }

    float accO[8][4] = {};
    float lacc[4] = {};
    const uint32_t ONE2 = 0x3C003C00u;

    // ldsm address components
    const int kb_row = ((lane >> 4) << 3) + (lane & 7);       // K b-frag row within 16
    const int kb_ko  = ((lane >> 3) & 1) << 3;                // K b-frag k offset
    const int vrow = ((lane >> 3) & 1) * 8 + (lane & 7);      // V trans row within 16
    const int vcol = ((lane >> 4) & 1) * 8;                   // V trans d offset

    for (int t = 0; t < NT; t++) {
        const int cur = t & 1;
        __syncthreads();   // everyone done computing on buffer (1-cur)
        if (t + 1 < NT) {
            const uint32_t kst = smbase + 2u * ((128u + 128u * (1 - cur)) * AST);
            const uint32_t vst = kst + 2u * (64u * AST);
            const __half* kn = kb + (size_t)(t + 1) * 64 * HIDD;
            const __half* vn = vb + (size_t)(t + 1) * 64 * HIDD;
            #pragma unroll
            for (int u = 0; u < 2; u++) {
                int f = tid + u * 256;
                int r = f >> 3, e8 = (f & 7) * 8;
                cpasync16(kst + 2u * (r * AST + e8), &kn[(size_t)r * HIDD + e8]);
                cpasync16(vst + 2u * (r * AST + e8), &vn[(size_t)r * HIDD + e8]);
            }
            asm volatile("cp.async.commit_group;");
            asm volatile("cp.async.wait_group 1;");
        } else {
            asm volatile("cp.async.wait_group 0;");
        }
        __syncthreads();   // current buffer visible to all

        const uint32_t ksb = smbase + 2u * ((128u + 128u * cur) * AST);
        const uint32_t vsb = ksb + 2u * (64u * AST);

        // S = Q K^T (log2 domain): K B-frags via non-trans ldsm
        float s[8][4] = {};
        #pragma unroll
        for (int kk = 0; kk < 4; kk++) {
            #pragma unroll
            for (int p = 0; p < 4; p++) {
                uint32_t b0, b1, b2, b3;
                uint32_t addr = ksb + 2u * (uint32_t)((p * 16 + kb_row) * AST + kk * 16 + kb_ko);
                ldsm_x4(b0, b1, b2, b3, addr);
                mma_f16(s[2 * p],     qa[kk][0], qa[kk][1], qa[kk][2], qa[kk][3], b0, b1);
                mma_f16(s[2 * p + 1], qa[kk][0], qa[kk][1], qa[kk][2], qa[kk][3], b2, b3);
            }
        }

        // P = exp2(S), packed straight into PV A-fragments (no smem round-trip)
        uint32_t pa[4][4];
        #pragma unroll
        for (int kk = 0; kk < 4; kk++) {
            pa[kk][0] = ex2h2(s[2 * kk][0],     s[2 * kk][1]);
            pa[kk][1] = ex2h2(s[2 * kk][2],     s[2 * kk][3]);
            pa[kk][2] = ex2h2(s[2 * kk + 1][0], s[2 * kk + 1][1]);
            pa[kk][3] = ex2h2(s[2 * kk + 1][2], s[2 * kk + 1][3]);
        }
        // row sums via ones-MMA, accumulated across all tiles
        #pragma unroll
        for (int kk = 0; kk < 4; kk++)
            mma_f16(lacc, pa[kk][0], pa[kk][1], pa[kk][2], pa[kk][3], ONE2, ONE2);

        // O += P V (V B-frags via trans ldsm)
        #pragma unroll
        for (int kk = 0; kk < 4; kk++) {
            #pragma unroll
            for (int nbp = 0; nbp < 4; nbp++) {
                uint32_t b0, b1, b2, b3;
                uint32_t addr = vsb + 2u * (uint32_t)((kk * 16 + vrow) * AST + nbp * 16 + vcol);
                ldsm_x4_trans(b0, b1, b2, b3, addr);
                mma_f16(accO[2 * nbp],     pa[kk][0], pa[kk][1], pa[kk][2], pa[kk][3], b0, b1);
                mma_f16(accO[2 * nbp + 1], pa[kk][0], pa[kk][1], pa[kk][2], pa[kk][3], b2, b3);
            }
        }
    }

    const int r0 = w * 16 + gid;
    const int r1 = r0 + 8;
    const float inv0 = 1.0f / lacc[0], inv1 = 1.0f / lacc[2];
    #pragma unroll
    for (int nb = 0; nb < 8; nb++) {
        int col = nb * 8 + 2 * tig;
        *(uint32_t*)&o[base + (size_t)(q0 + r0) * HIDD + col] =
            packh2(accO[nb][0] * inv0, accO[nb][1] * inv0);
        *(uint32_t*)&o[base + (size_t)(q0 + r1) * HIDD + col] =
            packh2(accO[nb][2] * inv1, accO[nb][3] * inv1);
    }
}

// ---------------- residual + LayerNorm (warp per row) ------------------------
__global__ void ln_kernel(const float* __restrict__ Qin, const float* __restrict__ o2,
                          const float* __restrict__ g, const float* __restrict__ bta,
                          float* __restrict__ out) {
    const int w = threadIdx.x >> 5, lane = threadIdx.x & 31;
    const int n = blockIdx.x * 8 + w;
    float y[8];
    float sum = 0.0f;
    #pragma unroll
    for (int u = 0; u < 2; u++) {
        float4 a = *(const float4*)&Qin[(size_t)n * HIDD + (u * 32 + lane) * 4];
        float4 c = *(const float4*)&o2[(size_t)n * HIDD + (u * 32 + lane) * 4];
        y[u * 4 + 0] = a.x + c.x; y[u * 4 + 1] = a.y + c.y;
        y[u * 4 + 2] = a.z + c.z; y[u * 4 + 3] = a.w + c.w;
        sum += y[u * 4 + 0] + y[u * 4 + 1] + y[u * 4 + 2] + y[u * 4 + 3];
    }
    #pragma unroll
    for (int off = 16; off >= 1; off >>= 1) sum += __shfl_xor_sync(0xffffffffu, sum, off);
    const float mu = sum * (1.0f / HIDD);
    float vs = 0.0f;
    #pragma unroll
    for (int i = 0; i < 8; i++) { y[i] -= mu; vs += y[i] * y[i]; }
    #pragma unroll
    for (int off = 16; off >= 1; off >>= 1) vs += __shfl_xor_sync(0xffffffffu, vs, off);
    const float rstd = rsqrtf(vs * (1.0f / HIDD) + 1e-5f);
    #pragma unroll
    for (int u = 0; u < 2; u++) {
        int c0 = (u * 32 + lane) * 4;
        float4 gg = *(const float4*)&g[c0];
        float4 bb = *(const float4*)&bta[c0];
        float4 ov;
        ov.x = y[u * 4 + 0] * rstd * gg.x + bb.x;
        ov.y = y[u * 4 + 1] * rstd * gg.y + bb.y;
        ov.z = y[u * 4 + 2] * rstd * gg.z + bb.z;
        ov.w = y[u * 4 + 3] * rstd * gg.w + bb.w;
        *(float4*)&out[(size_t)n * HIDD + c0] = ov;
    }
}

// -----------------------------------------------------------------------------
extern "C" void kernel_launch(void* const* d_in, const int* in_sizes, int n_in,
                              void* d_out, int out_size) {
    const float* inputs       = (const float*)d_in[0];
    const float* Q_in         = (const float*)d_in[1];
    const float* input_coords = (const float*)d_in[2];
    const float* Q_in_coords  = (const float*)d_in[3];
    const float* Wq           = (const float*)d_in[4];
    const float* Wk           = (const float*)d_in[5];
    const float* Wv           = (const float*)d_in[6];
    const float* in_proj_w    = (const float*)d_in[7];
    const float* in_proj_b    = (const float*)d_in[8];
    const float* out_proj_w   = (const float*)d_in[9];
    const float* out_proj_b   = (const float*)d_in[10];
    const float* ln_g         = (const float*)d_in[11];
    const float* ln_b         = (const float*)d_in[12];
    const float* pe_w1        = (const float*)d_in[13];
    const float* pe_b1        = (const float*)d_in[14];
    const float* pe_w2        = (const float*)d_in[15];
    const float* pe_b2        = (const float*)d_in[16];

    __half *ip, *qp, *Wc, *wo, *qd, *kd, *vd, *od;
    float *o2d;
    cudaGetSymbolAddress((void**)&ip,  g_ip);
    cudaGetSymbolAddress((void**)&qp,  g_qp);
    cudaGetSymbolAddress((void**)&Wc,  g_Wc);
    cudaGetSymbolAddress((void**)&wo,  g_wo);
    cudaGetSymbolAddress((void**)&qd,  g_q);
    cudaGetSymbolAddress((void**)&kd,  g_k);
    cudaGetSymbolAddress((void**)&vd,  g_v);
    cudaGetSymbolAddress((void**)&od,  g_o);
    cudaGetSymbolAddress((void**)&o2d, g_o2);

    const int ATTN_SMEM = 384 * AST * (int)sizeof(__half);   // Q + 2x(K,V) = 67584
    cudaFuncSetAttribute(attn_h_kernel, cudaFuncAttributeMaxDynamicSharedMemorySize, ATTN_SMEM);

    const float QSCALE = 0.125f * 1.4426950408889634f;   // (1/sqrt(64)) * log2(e)

    // launch order keeps attn at index 5 (ncu captures -s 5 -c 1)
    pos_mlp_kernel<<<dim3(BN / 4, 2), 128>>>(input_coords, Q_in_coords,
                                             pe_w1, pe_b1, pe_w2, pe_b2, ip, qp);
    concat_copy_kernel<<<dim3(BN * 64 / 256, 2), 256>>>(inputs, ip, Q_in, qp);
    wcombine_kernel<<<dim3(CATD / 16, HIDD / 16, 3), dim3(16, 16)>>>(in_proj_w, Wq, Wk, Wv, Wc);
    f2h_kernel<<<HIDD * HIDD / 4 / 256, 256>>>(out_proj_w, wo);
    gemm_qkv_kernel<<<dim3(4, BN / 64, 3), 256>>>(qp, ip, Wc, in_proj_b, QSCALE, qd, kd, vd);
    attn_h_kernel<<<dim3(SEQ / 128, BATCH * NHEAD), 256, ATTN_SMEM>>>(qd, kd, vd, od);
    gemm_out_kernel<<<dim3(4, BN / 64), 256>>>(od, wo, out_proj_b, o2d);
    ln_kernel<<<BN / 8, 256>>>(Q_in, o2d, ln_g, ln_b, (float*)d_out);
}

// round 14
// speedup vs baseline: 1.0026x; 1.0026x over previous
#include <cuda_runtime.h>
#include <cuda_fp16.h>
#include <cstdint>

#define BN    16384
#define HIDD  256
#define NHEAD 4
#define DHEAD 64
#define BATCH 8
#define SEQ   2048
#define CATD  288   // HID + POS

// ---------------- scratch (device globals; no allocation allowed) -------------
__device__ __half g_ip[BN * CATD];
__device__ __half g_qp[BN * CATD];
__device__ __half g_Wc[3 * HIDD * CATD];
__device__ __half g_wo[HIDD * HIDD];
__device__ __half g_q[BN * HIDD];
__device__ __half g_k[BN * HIDD];
__device__ __half g_v[BN * HIDD];
__device__ __half g_o[BN * HIDD];
__device__ float  g_o2[BN * HIDD];

// ---------------- helpers -----------------------------------------------------
__device__ __forceinline__ void mma_f16(float c[4], uint32_t a0, uint32_t a1,
                                        uint32_t a2, uint32_t a3,
                                        uint32_t b0, uint32_t b1) {
    asm volatile(
        "mma.sync.aligned.m16n8k16.row.col.f32.f16.f16.f32 "
        "{%0,%1,%2,%3}, {%4,%5,%6,%7}, {%8,%9}, {%0,%1,%2,%3};\n"
        : "+f"(c[0]), "+f"(c[1]), "+f"(c[2]), "+f"(c[3])
        : "r"(a0), "r"(a1), "r"(a2), "r"(a3), "r"(b0), "r"(b1));
}
__device__ __forceinline__ void ldsm_x4(uint32_t& r0, uint32_t& r1,
                                        uint32_t& r2, uint32_t& r3, uint32_t addr) {
    asm volatile("ldmatrix.sync.aligned.m8n8.x4.shared.b16 {%0,%1,%2,%3}, [%4];"
                 : "=r"(r0), "=r"(r1), "=r"(r2), "=r"(r3) : "r"(addr));
}
__device__ __forceinline__ void ldsm_x4_trans(uint32_t& r0, uint32_t& r1,
                                              uint32_t& r2, uint32_t& r3, uint32_t addr) {
    asm volatile("ldmatrix.sync.aligned.m8n8.x4.trans.shared.b16 {%0,%1,%2,%3}, [%4];"
                 : "=r"(r0), "=r"(r1), "=r"(r2), "=r"(r3) : "r"(addr));
}
__device__ __forceinline__ uint32_t ex2h2(float a, float b) {
    __half2 h = __floats2half2_rn(a, b);
    uint32_t in = *(uint32_t*)&h, out;
    asm("ex2.approx.f16x2 %0, %1;" : "=r"(out) : "r"(in));
    return out;
}
__device__ __forceinline__ uint32_t packh2(float a, float b) {
    __half2 h = __floats2half2_rn(a, b);
    return *(uint32_t*)&h;
}
__device__ __forceinline__ void cpasync16(uint32_t saddr, const void* g) {
    asm volatile("cp.async.cg.shared.global [%0], [%1], 16;" :: "r"(saddr), "l"(g));
}

// ---------------- pos2embed + 2-layer MLP (both coord sets in one launch) ----
__global__ void pos_mlp_kernel(const float* __restrict__ coordsA,
                               const float* __restrict__ coordsB,
                               const float* __restrict__ w1, const float* __restrict__ b1,
                               const float* __restrict__ w2, const float* __restrict__ b2,
                               __half* __restrict__ outA, __half* __restrict__ outB) {
    __shared__ float e_sh[4][96];
    __shared__ float h_sh[4][32];
    const int warp = threadIdx.x >> 5;
    const int lane = threadIdx.x & 31;
    const int n = blockIdx.x * 4 + warp;
    const float* coords = blockIdx.y ? coordsB : coordsA;
    __half* out = blockIdx.y ? outB : outA;

    const float TWO_PI = 6.283185307179586f;
    const float* c = coords + (size_t)n * 4;
    const float px = c[1] * TWO_PI;
    const float py = c[2] * TWO_PI;
    const float pz = c[3] * TWO_PI;

    const float dimt = 1.0f + (float)(lane >> 1) * (1.0f / 16.0f);
    const bool even = (lane & 1) == 0;
    // order (ey, ex, ez); NOTE reference bug: ez odd entries use cos(px)
    e_sh[warp][lane]      = even ? sinf(py / dimt) : cosf(py / dimt);
    e_sh[warp][32 + lane] = even ? sinf(px / dimt) : cosf(px / dimt);
    e_sh[warp][64 + lane] = even ? sinf(pz / dimt) : cosf(px / dimt);
    __syncwarp();

    float h = b1[lane];
    #pragma unroll 8
    for (int j = 0; j < 96; j++) h = fmaf(e_sh[warp][j], w1[lane * 96 + j], h);
    h_sh[warp][lane] = fmaxf(h, 0.0f);
    __syncwarp();

    float o = b2[lane];
    #pragma unroll
    for (int j = 0; j < 32; j++) o = fmaf(h_sh[warp][j], w2[lane * 32 + j], o);
    out[(size_t)n * CATD + HIDD + lane] = __float2half_rn(o);
}

// ---------------- fp32 rows -> fp16 rows inside 288-stride concat buffer -----
__global__ void concat_copy_kernel(const float* __restrict__ srcA, __half* __restrict__ dstA,
                                   const float* __restrict__ srcB, __half* __restrict__ dstB) {
    const float* src = blockIdx.y ? srcB : srcA;
    __half* dst = blockIdx.y ? dstB : dstA;
    int idx = blockIdx.x * blockDim.x + threadIdx.x;
    int n = idx >> 6, c4 = idx & 63;
    float4 v = ((const float4*)src)[(size_t)n * 64 + c4];
    uint2 u;
    u.x = packh2(v.x, v.y);
    u.y = packh2(v.z, v.w);
    *(uint2*)&dst[(size_t)n * CATD + c4 * 4] = u;
}

// ---------------- fp32 -> fp16 plain convert ---------------------------------
__global__ void f2h_kernel(const float* __restrict__ s, __half* __restrict__ d) {
    int i = blockIdx.x * blockDim.x + threadIdx.x;
    float4 v = ((const float4*)s)[i];
    uint2 u;
    u.x = packh2(v.x, v.y);
    u.y = packh2(v.z, v.w);
    *(uint2*)&d[(size_t)i * 4] = u;
}

// ---------------- Wc[m] = in_proj_w[m] @ W_m   (256x288), half out -----------
__global__ void wcombine_kernel(const float* __restrict__ in_proj_w,
                                const float* __restrict__ Wq,
                                const float* __restrict__ Wk,
                                const float* __restrict__ Wv,
                                __half* __restrict__ Wc) {
    const int m = blockIdx.z;
    const float* W = (m == 0) ? Wq : ((m == 1) ? Wk : Wv);
    const float* A = in_proj_w + (size_t)m * HIDD * HIDD;
    __shared__ float As[16][17];
    __shared__ float Bs[16][17];
    const int tx = threadIdx.x, ty = threadIdx.y;
    const int row = blockIdx.y * 16 + ty;
    const int col = blockIdx.x * 16 + tx;
    float acc = 0.0f;
    for (int kt = 0; kt < HIDD; kt += 16) {
        As[ty][tx] = A[row * HIDD + kt + tx];
        Bs[ty][tx] = W[(kt + ty) * CATD + col];
        __syncthreads();
        #pragma unroll
        for (int kk = 0; kk < 16; kk++) acc = fmaf(As[ty][kk], Bs[kk][tx], acc);
        __syncthreads();
    }
    Wc[(size_t)m * HIDD * CATD + row * CATD + col] = __float2half_rn(acc);
}

// ---------------- fp16 GEMM body: C[M,256] = (A@W^T + bias)*scale ------------
#define GST 40
template<int HOUT>
__device__ __forceinline__ void gemm_body(
        const __half* __restrict__ A, int K,
        const __half* __restrict__ W, const float* __restrict__ bias,
        float scale, void* __restrict__ Cv,
        __half* As, __half* Ws) {
    const int tid = threadIdx.x;
    const int w = tid >> 5, lane = tid & 31;
    const int gid = lane >> 2, tig = lane & 3;
    const int wr = w >> 1, wc = w & 1;
    const int m0 = blockIdx.y * 64, n0 = blockIdx.x * 64;
    float acc[4][4] = {};
    const int lr = tid >> 2, le8 = (tid & 3) * 8;
    for (int kt = 0; kt < K; kt += 32) {
        *(uint4*)&As[lr * GST + le8] = *(const uint4*)&A[(size_t)(m0 + lr) * K + kt + le8];
        *(uint4*)&Ws[lr * GST + le8] = *(const uint4*)&W[(size_t)(n0 + lr) * K + kt + le8];
        __syncthreads();
        #pragma unroll
        for (int kk = 0; kk < 2; kk++) {
            uint32_t a0 = *(uint32_t*)&As[(wr * 16 + gid) * GST + kk * 16 + 2 * tig];
            uint32_t a1 = *(uint32_t*)&As[(wr * 16 + gid + 8) * GST + kk * 16 + 2 * tig];
            uint32_t a2 = *(uint32_t*)&As[(wr * 16 + gid) * GST + kk * 16 + 2 * tig + 8];
            uint32_t a3 = *(uint32_t*)&As[(wr * 16 + gid + 8) * GST + kk * 16 + 2 * tig + 8];
            #pragma unroll
            for (int nb = 0; nb < 4; nb++) {
                uint32_t b0 = *(uint32_t*)&Ws[(wc * 32 + nb * 8 + gid) * GST + kk * 16 + 2 * tig];
                uint32_t b1 = *(uint32_t*)&Ws[(wc * 32 + nb * 8 + gid) * GST + kk * 16 + 2 * tig + 8];
                mma_f16(acc[nb], a0, a1, a2, a3, b0, b1);
            }
        }
        __syncthreads();
    }
    #pragma unroll
    for (int nb = 0; nb < 4; nb++) {
        int col = n0 + wc * 32 + nb * 8 + 2 * tig;
        float b0 = bias[col], b1 = bias[col + 1];
        float v00 = (acc[nb][0] + b0) * scale, v01 = (acc[nb][1] + b1) * scale;
        float v10 = (acc[nb][2] + b0) * scale, v11 = (acc[nb][3] + b1) * scale;
        int row0 = m0 + wr * 16 + gid;
        if (HOUT) {
            __half* C = (__half*)Cv;
            *(uint32_t*)&C[(size_t)row0 * HIDD + col] = packh2(v00, v01);
            *(uint32_t*)&C[(size_t)(row0 + 8) * HIDD + col] = packh2(v10, v11);
        } else {
            float* C = (float*)Cv;
            *(float2*)&C[(size_t)row0 * HIDD + col] = make_float2(v00, v01);
            *(float2*)&C[(size_t)(row0 + 8) * HIDD + col] = make_float2(v10, v11);
        }
    }
}

// merged q/k/v projection: blockIdx.z selects target
__global__ __launch_bounds__(256) void gemm_qkv_kernel(
        const __half* __restrict__ qp, const __half* __restrict__ ip,
        const __half* __restrict__ Wc, const float* __restrict__ in_proj_b,
        float qscale,
        __half* __restrict__ qd, __half* __restrict__ kd, __half* __restrict__ vd) {
    __shared__ __half As[64 * GST];
    __shared__ __half Ws[64 * GST];
    const int z = blockIdx.z;
    const __half* A = (z == 0) ? qp : ip;
    __half* C = (z == 0) ? qd : ((z == 1) ? kd : vd);
    gemm_body<1>(A, CATD, Wc + (size_t)z * HIDD * CATD, in_proj_b + z * HIDD,
                 (z == 0) ? qscale : 1.0f, C, As, Ws);
}

__global__ __launch_bounds__(256) void gemm_out_kernel(
        const __half* __restrict__ A, const __half* __restrict__ W,
        const float* __restrict__ bias, float* __restrict__ C) {
    __shared__ __half As[64 * GST];
    __shared__ __half Ws[64 * GST];
    gemm_body<0>(A, HIDD, W, bias, 1.0f, C, As, Ws);
}

// ---------------- flash attention, fp16 mma, register-resident P -------------
// grid (SEQ/128, B*H), block 256 (8 warps x 16 q rows). Q pre-scaled log2e/8.
// smem: Q[128xAST] + double-buffered K,V[64xAST each]
#define AST 88
#define NT  (SEQ / 64)
__global__ __launch_bounds__(256, 2) void attn_h_kernel(
        const __half* __restrict__ q, const __half* __restrict__ k,
        const __half* __restrict__ v, __half* __restrict__ o) {
    extern __shared__ __half sm[];
    __half* Qs = sm;                                  // 128 x AST
    // K/V stage c: sm + (128 + 128*c)*AST , V offset +64*AST
    const int tid = threadIdx.x;
    const int w = tid >> 5, lane = tid & 31;
    const int gid = lane >> 2, tig = lane & 3;
    const int bh = blockIdx.y;
    const int b = bh >> 2, h = bh & 3;
    const int q0 = blockIdx.x * 128;
    const size_t base = (size_t)b * SEQ * HIDD + h * DHEAD;
    const __half* qb = q + base;
    const __half* kb = k + base;
    const __half* vb = v + base;

    const uint32_t smbase = (uint32_t)__cvta_generic_to_shared(sm);
    const int ldr = tid >> 3, lde8 = (tid & 7) * 8;   // 256 thr -> 32 rows x 8 chunks? (64 rows: 2 iters)

    // load Q tile to smem
    #pragma unroll
    for (int u = 0; u < 4; u++) {
        int f = tid + u * 256;
        int r = f >> 3, e8 = (f & 7) * 8;
        *(uint4*)&Qs[r * AST + e8] = *(const uint4*)&qb[(size_t)(q0 + r) * HIDD + e8];
    }

    // prologue: async-load K/V tile 0 into stage 0
    {
        const uint32_t kst = smbase + 2u * (128u * AST);
        const uint32_t vst = kst + 2u * (64u * AST);
        #pragma unroll
        for (int u = 0; u < 2; u++) {
            int f = tid + u * 256;
            int r = f >> 3, e8 = (f & 7) * 8;
            cpasync16(kst + 2u * (r * AST + e8), &kb[(size_t)r * HIDD + e8]);
            cpasync16(vst + 2u * (r * AST + e8), &vb[(size_t)r * HIDD + e8]);
        }
        asm volatile("cp.async.commit_group;");
    }
    __syncthreads();   // Qs visible

    // preload Q A-fragments (4 k-blocks of 16)
    uint32_t qa[4][4];
    {
        const uint32_t qsb = smbase;
        const int row = w * 16 + (lane & 15);
        const int ko = (lane >> 4) * 8;
        #pragma unroll
        for (int kk = 0; kk < 4; kk++) {
            uint32_t addr = qsb + 2u * (uint32_t)(row * AST + kk * 16 + ko);
            ldsm_x4(qa[kk][0], qa[kk][1], qa[kk][2], qa[kk][3], addr);
        }
    }

    float accO[8][4] = {};
    float lacc[4] = {};
    const uint32_t ONE2 = 0x3C003C00u;

    // ldsm address components
    const int kb_row = ((lane >> 4) << 3) + (lane & 7);       // K b-frag row within 16
    const int kb_ko  = ((lane >> 3) & 1) << 3;                // K b-frag k offset
    const int vrow = ((lane >> 3) & 1) * 8 + (lane & 7);      // V trans row within 16
    const int vcol = ((lane >> 4) & 1) * 8;                   // V trans d offset

    for (int t = 0; t < NT; t++) {
        const int cur = t & 1;
        __syncthreads();   // everyone done computing on buffer (1-cur)
        if (t + 1 < NT) {
            const uint32_t kst = smbase + 2u * ((128u + 128u * (1 - cur)) * AST);
            const uint32_t vst = kst + 2u * (64u * AST);
            const __half* kn = kb + (size_t)(t + 1) * 64 * HIDD;
            const __half* vn = vb + (size_t)(t + 1) * 64 * HIDD;
            #pragma unroll
            for (int u = 0; u < 2; u++) {
                int f = tid + u * 256;
                int r = f >> 3, e8 = (f & 7) * 8;
                cpasync16(kst + 2u * (r * AST + e8), &kn[(size_t)r * HIDD + e8]);
                cpasync16(vst + 2u * (r * AST + e8), &vn[(size_t)r * HIDD + e8]);
            }
            asm volatile("cp.async.commit_group;");
            asm volatile("cp.async.wait_group 1;");
        } else {
            asm volatile("cp.async.wait_group 0;");
        }
        __syncthreads();   // current buffer visible to all

        const uint32_t ksb = smbase + 2u * ((128u + 128u * cur) * AST);
        const uint32_t vsb = ksb + 2u * (64u * AST);

        // S = Q K^T (log2 domain): K B-frags via non-trans ldsm
        float s[8][4] = {};
        #pragma unroll
        for (int kk = 0; kk < 4; kk++) {
            #pragma unroll
            for (int p = 0; p < 4; p++) {
                uint32_t b0, b1, b2, b3;
                uint32_t addr = ksb + 2u * (uint32_t)((p * 16 + kb_row) * AST + kk * 16 + kb_ko);
                ldsm_x4(b0, b1, b2, b3, addr);
                mma_f16(s[2 * p],     qa[kk][0], qa[kk][1], qa[kk][2], qa[kk][3], b0, b1);
                mma_f16(s[2 * p + 1], qa[kk][0], qa[kk][1], qa[kk][2], qa[kk][3], b2, b3);
            }
        }

        // P = exp2(S), packed straight into PV A-fragments (no smem round-trip)
        uint32_t pa[4][4];
        #pragma unroll
        for (int kk = 0; kk < 4; kk++) {
            pa[kk][0] = ex2h2(s[2 * kk][0],     s[2 * kk][1]);
            pa[kk][1] = ex2h2(s[2 * kk][2],     s[2 * kk][3]);
            pa[kk][2] = ex2h2(s[2 * kk + 1][0], s[2 * kk + 1][1]);
            pa[kk][3] = ex2h2(s[2 * kk + 1][2], s[2 * kk + 1][3]);
        }
        // row sums via ones-MMA, accumulated across all tiles
        #pragma unroll
        for (int kk = 0; kk < 4; kk++)
            mma_f16(lacc, pa[kk][0], pa[kk][1], pa[kk][2], pa[kk][3], ONE2, ONE2);

        // O += P V (V B-frags via trans ldsm)
        #pragma unroll
        for (int kk = 0; kk < 4; kk++) {
            #pragma unroll
            for (int nbp = 0; nbp < 4; nbp++) {
                uint32_t b0, b1, b2, b3;
                uint32_t addr = vsb + 2u * (uint32_t)((kk * 16 + vrow) * AST + nbp * 16 + vcol);
                ldsm_x4_trans(b0, b1, b2, b3, addr);
                mma_f16(accO[2 * nbp],     pa[kk][0], pa[kk][1], pa[kk][2], pa[kk][3], b0, b1);
                mma_f16(accO[2 * nbp + 1], pa[kk][0], pa[kk][1], pa[kk][2], pa[kk][3], b2, b3);
            }
        }
    }

    const int r0 = w * 16 + gid;
    const int r1 = r0 + 8;
    const float inv0 = 1.0f / lacc[0], inv1 = 1.0f / lacc[2];
    #pragma unroll
    for (int nb = 0; nb < 8; nb++) {
        int col = nb * 8 + 2 * tig;
        *(uint32_t*)&o[base + (size_t)(q0 + r0) * HIDD + col] =
            packh2(accO[nb][0] * inv0, accO[nb][1] * inv0);
        *(uint32_t*)&o[base + (size_t)(q0 + r1) * HIDD + col] =
            packh2(accO[nb][2] * inv1, accO[nb][3] * inv1);
    }
}

// ---------------- residual + LayerNorm (warp per row) ------------------------
__global__ void ln_kernel(const float* __restrict__ Qin, const float* __restrict__ o2,
                          const float* __restrict__ g, const float* __restrict__ bta,
                          float* __restrict__ out) {
    const int w = threadIdx.x >> 5, lane = threadIdx.x & 31;
    const int n = blockIdx.x * 8 + w;
    float y[8];
    float sum = 0.0f;
    #pragma unroll
    for (int u = 0; u < 2; u++) {
        float4 a = *(const float4*)&Qin[(size_t)n * HIDD + (u * 32 + lane) * 4];
        float4 c = *(const float4*)&o2[(size_t)n * HIDD + (u * 32 + lane) * 4];
        y[u * 4 + 0] = a.x + c.x; y[u * 4 + 1] = a.y + c.y;
        y[u * 4 + 2] = a.z + c.z; y[u * 4 + 3] = a.w + c.w;
        sum += y[u * 4 + 0] + y[u * 4 + 1] + y[u * 4 + 2] + y[u * 4 + 3];
    }
    #pragma unroll
    for (int off = 16; off >= 1; off >>= 1) sum += __shfl_xor_sync(0xffffffffu, sum, off);
    const float mu = sum * (1.0f / HIDD);
    float vs = 0.0f;
    #pragma unroll
    for (int i = 0; i < 8; i++) { y[i] -= mu; vs += y[i] * y[i]; }
    #pragma unroll
    for (int off = 16; off >= 1; off >>= 1) vs += __shfl_xor_sync(0xffffffffu, vs, off);
    const float rstd = rsqrtf(vs * (1.0f / HIDD) + 1e-5f);
    #pragma unroll
    for (int u = 0; u < 2; u++) {
        int c0 = (u * 32 + lane) * 4;
        float4 gg = *(const float4*)&g[c0];
        float4 bb = *(const float4*)&bta[c0];
        float4 ov;
        ov.x = y[u * 4 + 0] * rstd * gg.x + bb.x;
        ov.y = y[u * 4 + 1] * rstd * gg.y + bb.y;
        ov.z = y[u * 4 + 2] * rstd * gg.z + bb.z;
        ov.w = y[u * 4 + 3] * rstd * gg.w + bb.w;
        *(float4*)&out[(size_t)n * HIDD + c0] = ov;
    }
}

// -----------------------------------------------------------------------------
extern "C" void kernel_launch(void* const* d_in, const int* in_sizes, int n_in,
                              void* d_out, int out_size) {
    const float* inputs       = (const float*)d_in[0];
    const float* Q_in         = (const float*)d_in[1];
    const float* input_coords = (const float*)d_in[2];
    const float* Q_in_coords  = (const float*)d_in[3];
    const float* Wq           = (const float*)d_in[4];
    const float* Wk           = (const float*)d_in[5];
    const float* Wv           = (const float*)d_in[6];
    const float* in_proj_w    = (const float*)d_in[7];
    const float* in_proj_b    = (const float*)d_in[8];
    const float* out_proj_w   = (const float*)d_in[9];
    const float* out_proj_b   = (const float*)d_in[10];
    const float* ln_g         = (const float*)d_in[11];
    const float* ln_b         = (const float*)d_in[12];
    const float* pe_w1        = (const float*)d_in[13];
    const float* pe_b1        = (const float*)d_in[14];
    const float* pe_w2        = (const float*)d_in[15];
    const float* pe_b2        = (const float*)d_in[16];

    __half *ip, *qp, *Wc, *wo, *qd, *kd, *vd, *od;
    float *o2d;
    cudaGetSymbolAddress((void**)&ip,  g_ip);
    cudaGetSymbolAddress((void**)&qp,  g_qp);
    cudaGetSymbolAddress((void**)&Wc,  g_Wc);
    cudaGetSymbolAddress((void**)&wo,  g_wo);
    cudaGetSymbolAddress((void**)&qd,  g_q);
    cudaGetSymbolAddress((void**)&kd,  g_k);
    cudaGetSymbolAddress((void**)&vd,  g_v);
    cudaGetSymbolAddress((void**)&od,  g_o);
    cudaGetSymbolAddress((void**)&o2d, g_o2);

    const int ATTN_SMEM = 384 * AST * (int)sizeof(__half);   // Q + 2x(K,V) = 67584
    cudaFuncSetAttribute(attn_h_kernel, cudaFuncAttributeMaxDynamicSharedMemorySize, ATTN_SMEM);

    const float QSCALE = 0.125f * 1.4426950408889634f;   // (1/sqrt(64)) * log2(e)

    // launch order keeps attn at index 5 (ncu captures -s 5 -c 1)
    pos_mlp_kernel<<<dim3(BN / 4, 2), 128>>>(input_coords, Q_in_coords,
                                             pe_w1, pe_b1, pe_w2, pe_b2, ip, qp);
    concat_copy_kernel<<<dim3(BN * 64 / 256, 2), 256>>>(inputs, ip, Q_in, qp);
    wcombine_kernel<<<dim3(CATD / 16, HIDD / 16, 3), dim3(16, 16)>>>(in_proj_w, Wq, Wk, Wv, Wc);
    f2h_kernel<<<HIDD * HIDD / 4 / 256, 256>>>(out_proj_w, wo);
    gemm_qkv_kernel<<<dim3(4, BN / 64, 3), 256>>>(qp, ip, Wc, in_proj_b, QSCALE, qd, kd, vd);
    attn_h_kernel<<<dim3(SEQ / 128, BATCH * NHEAD), 256, ATTN_SMEM>>>(qd, kd, vd, od);
    gemm_out_kernel<<<dim3(4, BN / 64), 256>>>(od, wo, out_proj_b, o2d);
    ln_kernel<<<BN / 8, 256>>>(Q_in, o2d, ln_g, ln_b, (float*)d_out);
}